// round 16
// baseline (speedup 1.0000x reference)
#include <cuda_runtime.h>
#include <math.h>

#define NB 64
#define NN 128
#define NN2 16384
#define NF 21
#define NE 512
#define FD 1150
#define P 129

__device__ float g_L[NB*NN2];
__device__ float g_D[NB*NF*NN2];
__device__ float g_A[NB*NN2];
__device__ float g_y[NB*NN*FD];
__device__ float g_norm[NB*NN];
__device__ float g_emb[NB*FD];
__device__ float g_spp[NB*4];
__device__ float g_dist[NB*NB];

// ---- K1: bit-exact normalized Laplacian ----
__global__ void __launch_bounds__(256,1) k_L(const int* __restrict__ es, const int* __restrict__ ed){
  __shared__ unsigned adj[NN][4]; __shared__ float dinv[NN];
  int g=blockIdx.x, t=threadIdx.x;
  for(int i=t;i<NN*4;i+=256) ((unsigned*)adj)[i]=0u;
  __syncthreads();
  for(int e=t;e<NE;e+=256){ int s=es[g*NE+e], d=ed[g*NE+e];
    atomicOr(&adj[s][d>>5],1u<<(d&31)); atomicOr(&adj[d][s>>5],1u<<(s&31)); }
  __syncthreads();
  if(t<NN){ int dg=__popc(adj[t][0])+__popc(adj[t][1])+__popc(adj[t][2])+__popc(adj[t][3]);
    dinv[t]= dg>0 ? __fdiv_rn(1.0f, __fsqrt_rn((float)dg)) : 0.0f; }
  __syncthreads();
  for(int idx=t;idx<NN2;idx+=256){ int i=idx>>7,j=idx&127;
    unsigned bit=(adj[i][j>>5]>>(j&31))&1u;
    float T = bit ? __fmul_rn(dinv[i],dinv[j]) : 0.0f;
    float v = (i==j) ? __fsub_rn(1.0f,T) : (-T);
    g_L[g*NN2+idx]=v; }
}

// ---- K2a: B = fl(fl((L-bI)^2)^2) + aI  (single smem buffer, 2 CTA/SM) ----
__global__ void __launch_bounds__(512,2) k_p4(){
  extern __shared__ float sM[];   // 128*129
  int blk=blockIdx.x, g=blk/NF, f=blk%NF, t=threadIdx.x, r=t>>4, c=t&15;
  float bf=(float)(0.1*(double)f);
  const float af=(float)6.250000000000001e-06;
  for(int idx=t;idx<NN2;idx+=512){ int i=idx>>7,j=idx&127;
    float v=g_L[g*NN2+idx];
    if(i==j) v=__fsub_rn(v,bf);
    sM[i*P+j]=v; }
  __syncthreads();
  float a32[4][8];
#pragma unroll
  for(int q=0;q<4;q++)
#pragma unroll
    for(int p=0;p<8;p++) a32[q][p]=0.f;
  for(int k=0;k<NN;k++){ float av[4],bv[8];
#pragma unroll
    for(int q=0;q<4;q++) av[q]=sM[(r+32*q)*P+k];
#pragma unroll
    for(int p=0;p<8;p++) bv[p]=sM[k*P+c+16*p];
#pragma unroll
    for(int q=0;q<4;q++)
#pragma unroll
      for(int p=0;p<8;p++) a32[q][p]=__fmaf_rn(av[q],bv[p],a32[q][p]); }
  __syncthreads();
#pragma unroll
  for(int q=0;q<4;q++)
#pragma unroll
    for(int p=0;p<8;p++) sM[(r+32*q)*P+c+16*p]=a32[q][p];
  __syncthreads();
#pragma unroll
  for(int q=0;q<4;q++)
#pragma unroll
    for(int p=0;p<8;p++) a32[q][p]=0.f;
  for(int k=0;k<NN;k++){ float av[4],bv[8];
#pragma unroll
    for(int q=0;q<4;q++) av[q]=sM[(r+32*q)*P+k];
#pragma unroll
    for(int p=0;p<8;p++) bv[p]=sM[k*P+c+16*p];
#pragma unroll
    for(int q=0;q<4;q++)
#pragma unroll
      for(int p=0;p<8;p++) a32[q][p]=__fmaf_rn(av[q],bv[p],a32[q][p]); }
  float* B=g_D+(size_t)blk*NN2;
#pragma unroll
  for(int q=0;q<4;q++){ int i=r+32*q;
#pragma unroll
    for(int p=0;p<8;p++){ int j=c+16*p;
      float v=a32[q][p];
      if(i==j) v=__fadd_rn(v,af);
      B[i*NN+j]=v; } }
}

// ---- K2b: W = sqrt2*a * inv(B), fp32 GJ, lookahead-pipelined (1 bar/step) ----
__global__ void __launch_bounds__(512,2) k_inv(){
  __shared__ float cb[2][NN];
  __shared__ float rb[2][NN];
  __shared__ float pvv[2];
  int blk=blockIdx.x, t=threadIdx.x, r=t>>4, c=t&15;
  float* B=g_D+(size_t)blk*NN2;
  float m[4][8];
#pragma unroll
  for(int q=0;q<4;q++)
#pragma unroll
    for(int p=0;p<8;p++) m[q][p]=B[(r+32*q)*NN+c+16*p];
  // initial publish for k=0 (par=0)
  if(c==0){
#pragma unroll
    for(int q=0;q<4;q++) cb[0][r+32*q]=m[q][0];
    if(r==0) pvv[0]=__fdiv_rn(1.0f,m[0][0]);
  }
  if(r==0){
#pragma unroll
    for(int p=0;p<8;p++) rb[0][c+16*p]=m[0][p];
  }
#pragma unroll 1
  for(int k=0;k<NN;k++){
    int par=k&1, kc=k&15, kr=k&31, pk=k>>4, qk=k>>5;
    __syncthreads();
    float pinv=pvv[par];
    float rv[8];
#pragma unroll
    for(int p=0;p<8;p++) rv[p]=rb[par][c+16*p];
    float nfq[4];
#pragma unroll
    for(int q=0;q<4;q++) nfq[q]=-__fmul_rn(cb[par][r+32*q],pinv);
    // ---- lookahead: publish row/col/pivot for step k+1 (bit-equal to bulk results) ----
    if(k<NN-1){
      int kc1=(k+1)&15, kr1=(k+1)&31, pk1=(k+1)>>4, qk1=(k+1)>>5, par1=par^1;
      if(r==kr1){
#pragma unroll
        for(int q=0;q<4;q++) if(q==qk1){
#pragma unroll
          for(int p=0;p<8;p++){
            int j=c+16*p;
            float v=__fmaf_rn(nfq[q],rv[p],m[q][p]);
            if(j==k) v=nfq[q];                     // col-k fixup on row k+1
            rb[par1][j]=v;
          }
        }
      }
      if(c==kc1){
#pragma unroll
        for(int p=0;p<8;p++) if(p==pk1){
#pragma unroll
          for(int q=0;q<4;q++){
            int i=r+32*q;
            float v=__fmaf_rn(nfq[q],rv[p],m[q][p]);
            if(i==k) v=__fmul_rn(rv[p],pinv);      // row-k fixup on col k+1
            cb[par1][i]=v;
            if(i==k+1) pvv[par1]=__fdiv_rn(1.0f,v);
          }
        }
      }
    }
    // ---- bulk: pure-FMA rank-1 update ----
#pragma unroll
    for(int q=0;q<4;q++)
#pragma unroll
      for(int p=0;p<8;p++) m[q][p]=__fmaf_rn(nfq[q],rv[p],m[q][p]);
    // fixup row k
    if(r==kr){
#pragma unroll
      for(int q=0;q<4;q++) if(q==qk){
#pragma unroll
        for(int p=0;p<8;p++){ int j=c+16*p;
          m[q][p] = (j==k) ? pinv : __fmul_rn(rv[p],pinv); }
      }
    }
    // fixup col k
    if(c==kc){
#pragma unroll
      for(int p=0;p<8;p++) if(p==pk){
#pragma unroll
        for(int q=0;q<4;q++){ int i=r+32*q;
          if(i!=k) m[q][p]=nfq[q]; }
      }
    }
  }
  const float scf=(float)8.838834764831846e-06;
#pragma unroll
  for(int q=0;q<4;q++)
#pragma unroll
    for(int p=0;p<8;p++)
      B[(r+32*q)*NN+c+16*p]=__fmul_rn(scf,m[q][p]);
}

// ---- K3: A_hat = I - sum_f Cn[f]*D_f ----
__global__ void __launch_bounds__(512,1) k_comb(const float* __restrict__ C){
  __shared__ float cn[NF];
  int g=blockIdx.x, t=threadIdx.x;
  if(t==0){ float s=0; for(int f=0;f<NF;f++) s=__fmaf_rn(C[f],C[f],s);
    float nv=fmaxf(__fsqrt_rn(s),1e-12f);
    for(int f=0;f<NF;f++) cn[f]=__fdiv_rn(C[f],nv); }
  __syncthreads();
  int idx=blockIdx.y*512+t; int i=idx>>7,j=idx&127;
  float s=0;
  for(int f=0;f<NF;f++) s=__fmaf_rn(cn[f],g_D[((size_t)(g*NF+f))*NN2+idx],s);
  g_A[g*NN2+idx]=(i==j)?__fsub_rn(1.0f,s):(-s);
}

// ---- K4: y = A_hat @ feats ----
__global__ void __launch_bounds__(256,2) k_y(const float* __restrict__ x, const float* __restrict__ rs){
  extern __shared__ float sm[];
  float* sA=sm;            // 128*129
  float* sF=sm+NN*P;       // 128*65
  int g=blockIdx.x, cb2=blockIdx.y, t=threadIdx.x, r=t>>4, c=t&15;
  const float scl=(float)sqrt(1.0/1118.0);
  for(int i=t;i<NN2;i+=256) sA[(i>>7)*P+(i&127)]=g_A[g*NN2+i];
  for(int i=t;i<NN*64;i+=256){ int k=i>>6, cc=i&63; int col=cb2*64+cc; float v=0;
    if(col<FD) v=(col<32)? x[(g*NN+k)*32+col] : __fmul_rn(rs[(g*NN+k)*1118+col-32],scl);
    sF[k*65+cc]=v; }
  __syncthreads();
  float a[8][4];
#pragma unroll
  for(int q=0;q<8;q++)
#pragma unroll
    for(int p=0;p<4;p++) a[q][p]=0.f;
  for(int k=0;k<NN;k++){ float av[8],bv[4];
#pragma unroll
    for(int q=0;q<8;q++) av[q]=sA[(r+16*q)*P+k];
#pragma unroll
    for(int p=0;p<4;p++) bv[p]=sF[k*65+c+16*p];
#pragma unroll
    for(int q=0;q<8;q++)
#pragma unroll
      for(int p=0;p<4;p++) a[q][p]=__fmaf_rn(av[q],bv[p],a[q][p]); }
#pragma unroll
  for(int q=0;q<8;q++)
#pragma unroll
    for(int p=0;p<4;p++){ int col=cb2*64+c+16*p;
      if(col<FD) g_y[((size_t)g*NN+r+16*q)*FD+col]=a[q][p]; }
}

// ---- K5: row norms ----
__global__ void k_norm(){
  int g=blockIdx.x, t=threadIdx.x; float s=0;
  const float* yp=g_y+((size_t)g*NN+t)*FD;
  for(int c=0;c<FD;c++){ float v=yp[c]; s=__fmaf_rn(v,v,s); }
  g_norm[g*NN+t]=fmaxf(__fsqrt_rn(s),1e-12f);
}

// ---- K6: gram band -> sum |z z^T| partial ----
__global__ void __launch_bounds__(512,1) k_gram(){
  __shared__ float sY[NN*33];
  __shared__ float red[512];
  int g=blockIdx.x, band=blockIdx.y, t=threadIdx.x;
  int r2=t>>6, c2=t&63;
  float a[4][2];
#pragma unroll
  for(int u=0;u<4;u++)
#pragma unroll
    for(int v=0;v<2;v++) a[u][v]=0.f;
  for(int ch=0;ch<36;ch++){
    __syncthreads();
    for(int i=t;i<NN*32;i+=512){ int row=i>>5, cc=i&31; int col=ch*32+cc;
      sY[row*33+cc]=(col<FD)?g_y[((size_t)g*NN+row)*FD+col]:0.f; }
    __syncthreads();
    for(int kk=0;kk<32;kk++){ float va[4],vb[2];
#pragma unroll
      for(int u=0;u<4;u++) va[u]=sY[(band*32+r2+8*u)*33+kk];
#pragma unroll
      for(int v=0;v<2;v++) vb[v]=sY[(c2+64*v)*33+kk];
#pragma unroll
      for(int u=0;u<4;u++)
#pragma unroll
        for(int v=0;v<2;v++) a[u][v]=__fmaf_rn(va[u],vb[v],a[u][v]); }
  }
  float part=0;
#pragma unroll
  for(int u=0;u<4;u++){ float ni=g_norm[g*NN+band*32+r2+8*u];
#pragma unroll
    for(int v=0;v<2;v++){ float nj=g_norm[g*NN+c2+64*v];
      part+=__fdiv_rn(fabsf(a[u][v]),__fmul_rn(ni,nj)); } }
  red[t]=part; __syncthreads();
  for(int s=256;s>0;s>>=1){ if(t<s) red[t]+=red[t+s]; __syncthreads(); }
  if(t==0) g_spp[g*4+band]=red[0];
}

// ---- K7: emb means ----
__global__ void k_emb(){
  int g=blockIdx.x, c=blockIdx.y*128+threadIdx.x;
  if(c>=FD) return;
  float s=0;
  for(int i=0;i<NN;i++) s+=g_y[((size_t)g*NN+i)*FD+c];
  g_emb[g*FD+c]=s*(1.0f/NN);
}

// ---- K8: pairwise distances ----
__global__ void k_dist(){
  int i=blockIdx.x, j=threadIdx.x;
  const float* ei=g_emb+(size_t)i*FD; const float* ej=g_emb+(size_t)j*FD;
  float d2=0;
  for(int c=0;c<FD;c++){ float d=ei[c]-ej[c]; d2=__fmaf_rn(d,d,d2); }
  g_dist[i*NB+j]=(d2>0.f)?__fsqrt_rn(d2):0.f;
}

// ---- K9: final scalar ----
__global__ void __launch_bounds__(256,1) k_fin(const float* __restrict__ C, float* out){
  __shared__ float rp[256], rn[256];
  int t=threadIdx.x;
  float hl1=0,hl2=0;
  for(int cls=0;cls<4;cls++){
    float ps=0,ns=0;
    for(int p=t;p<NB*NB;p+=256){ int i=p>>6,j=p&63;
      bool pi=((i&3)==cls), pj=((j&3)==cls);
      float d=g_dist[p];
      if(pi&&pj) ps+=d; else if(!pi&&!pj) ns+=d; }
    rp[t]=ps; rn[t]=ns; __syncthreads();
    for(int s=128;s>0;s>>=1){ if(t<s){ rp[t]+=rp[t+s]; rn[t]+=rn[t+s]; } __syncthreads(); }
    if(t==0){ float pm=rp[0]/(16.0f*16.0f), nm=rn[0]/(48.0f*48.0f);
      hl1+=(-nm)/0.25f; hl2+=pm; }
    __syncthreads();
  }
  if(t==0){
    float sf=0, lb=logf(64.0f);
    for(int i=0;i<NB;i++){
      float sp=-(g_spp[i*4]+g_spp[i*4+1]+g_spp[i*4+2]+g_spp[i*4+3])/16384.0f;
      sf+=sp*expf(-(float)(NB-i)*lb); }
    float l1=0,l2=0;
    for(int f=0;f<NF;f++){ l1+=fabsf(C[f]); l2=__fmaf_rn(C[f],C[f],l2); }
    l2=fmaxf(__fsqrt_rn(l2),1e-12f);
    float dims=__fsqrt_rn(21.0f);
    float sc=(dims-__fdiv_rn(l1,l2))/(dims-1.0f);
    *out=sc+hl2+hl1+sf;
  }
}

extern "C" void kernel_launch(void* const* d_in, const int* in_sizes, int n_in,
                              void* d_out, int out_size){
  const float* x=(const float*)d_in[0];
  const float* rs=(const float*)d_in[1];
  const float* C=(const float*)d_in[2];
  const int* es=(const int*)d_in[3];
  const int* ed=(const int*)d_in[4];
  float* out=(float*)d_out;
  static bool init=false;
  if(!init){
    cudaFuncSetAttribute(k_p4, cudaFuncAttributeMaxDynamicSharedMemorySize, NN*P*4);
    cudaFuncSetAttribute(k_y, cudaFuncAttributeMaxDynamicSharedMemorySize, NN*P*4+NN*65*4);
    init=true;
  }
  k_L<<<NB,256>>>(es,ed);
  k_p4<<<NB*NF,512,NN*P*4>>>();
  k_inv<<<NB*NF,512>>>();
  k_comb<<<dim3(NB,32),512>>>(C);
  k_y<<<dim3(NB,18),256,NN*P*4+NN*65*4>>>(x,rs);
  k_norm<<<NB,NN>>>();
  k_gram<<<dim3(NB,4),512>>>();
  k_emb<<<dim3(NB,9),128>>>();
  k_dist<<<NB,NB>>>();
  k_fin<<<1,256>>>(C,out);
}

// round 17
// speedup vs baseline: 1.0495x; 1.0495x over previous
#include <cuda_runtime.h>
#include <math.h>

#define NB 64
#define NN 128
#define NN2 16384
#define NF 21
#define NE 512
#define FD 1150
#define P 129
#define P2 132

__device__ float g_L[NB*NN2];
__device__ float g_D[NB*NF*NN2];
__device__ float g_A[NB*NN2];
__device__ float g_y[NB*NN*FD];
__device__ float g_norm[NB*NN];
__device__ float g_emb[NB*FD];
__device__ float g_spp[NB*4];
__device__ float g_dist[NB*NB];

// ---- K1: bit-exact normalized Laplacian ----
__global__ void __launch_bounds__(256,1) k_L(const int* __restrict__ es, const int* __restrict__ ed){
  __shared__ unsigned adj[NN][4]; __shared__ float dinv[NN];
  int g=blockIdx.x, t=threadIdx.x;
  for(int i=t;i<NN*4;i+=256) ((unsigned*)adj)[i]=0u;
  __syncthreads();
  for(int e=t;e<NE;e+=256){ int s=es[g*NE+e], d=ed[g*NE+e];
    atomicOr(&adj[s][d>>5],1u<<(d&31)); atomicOr(&adj[d][s>>5],1u<<(s&31)); }
  __syncthreads();
  if(t<NN){ int dg=__popc(adj[t][0])+__popc(adj[t][1])+__popc(adj[t][2])+__popc(adj[t][3]);
    dinv[t]= dg>0 ? __fdiv_rn(1.0f, __fsqrt_rn((float)dg)) : 0.0f; }
  __syncthreads();
  for(int idx=t;idx<NN2;idx+=256){ int i=idx>>7,j=idx&127;
    unsigned bit=(adj[i][j>>5]>>(j&31))&1u;
    float T = bit ? __fmul_rn(dinv[i],dinv[j]) : 0.0f;
    float v = (i==j) ? __fsub_rn(1.0f,T) : (-T);
    g_L[g*NN2+idx]=v; }
}

// ---- K2a: B = fl(fl((L-bI)^2)^2) + aI ; 8x8 tiles, 256 thr, float4 LDS ----
__global__ void __launch_bounds__(256,2) k_p4(){
  extern __shared__ float sM[];   // 128*132
  int blk=blockIdx.x, g=blk/NF, f=blk%NF, t=threadIdx.x, r=t>>4, c=t&15;
  float bf=(float)(0.1*(double)f);
  const float af=(float)6.250000000000001e-06;
  for(int idx=t;idx<NN2;idx+=256){ int i=idx>>7,j=idx&127;
    float v=g_L[g*NN2+idx];
    if(i==j) v=__fsub_rn(v,bf);
    sM[i*P2+j]=v; }
  __syncthreads();
  float acc[8][8];
#pragma unroll
  for(int q=0;q<8;q++)
#pragma unroll
    for(int p=0;p<8;p++) acc[q][p]=0.f;
  for(int k=0;k<NN;k++){
    float av[8];
#pragma unroll
    for(int q=0;q<8;q++) av[q]=sM[(r*8+q)*P2+k];
    float4 b0=*(const float4*)&sM[k*P2+c*8];
    float4 b1=*(const float4*)&sM[k*P2+c*8+4];
    float bv[8]={b0.x,b0.y,b0.z,b0.w,b1.x,b1.y,b1.z,b1.w};
#pragma unroll
    for(int q=0;q<8;q++)
#pragma unroll
      for(int p=0;p<8;p++) acc[q][p]=__fmaf_rn(av[q],bv[p],acc[q][p]);
  }
  __syncthreads();
#pragma unroll
  for(int q=0;q<8;q++)
#pragma unroll
    for(int p=0;p<8;p++) sM[(r*8+q)*P2+c*8+p]=acc[q][p];
  __syncthreads();
#pragma unroll
  for(int q=0;q<8;q++)
#pragma unroll
    for(int p=0;p<8;p++) acc[q][p]=0.f;
  for(int k=0;k<NN;k++){
    float av[8];
#pragma unroll
    for(int q=0;q<8;q++) av[q]=sM[(r*8+q)*P2+k];
    float4 b0=*(const float4*)&sM[k*P2+c*8];
    float4 b1=*(const float4*)&sM[k*P2+c*8+4];
    float bv[8]={b0.x,b0.y,b0.z,b0.w,b1.x,b1.y,b1.z,b1.w};
#pragma unroll
    for(int q=0;q<8;q++)
#pragma unroll
      for(int p=0;p<8;p++) acc[q][p]=__fmaf_rn(av[q],bv[p],acc[q][p]);
  }
  float* B=g_D+(size_t)blk*NN2;
#pragma unroll
  for(int q=0;q<8;q++){ int i=r*8+q;
#pragma unroll
    for(int p=0;p<8;p++){ int j=c*8+p;
      float v=acc[q][p];
      if(i==j) v=__fadd_rn(v,af);
      B[i*NN+j]=v; } }
}

// ---- K2b: W = sqrt2*a*inv(B); 8x8 tiles, 256 thr, float4 LDS, 1 bar/step ----
__global__ void __launch_bounds__(256,2) k_inv(){
  __shared__ float cb[2][NN];
  __shared__ float rb[2][NN];
  __shared__ float pvv[2];
  int blk=blockIdx.x, t=threadIdx.x, r=t>>4, c=t&15;
  float* B=g_D+(size_t)blk*NN2;
  float m[8][8];
#pragma unroll
  for(int q=0;q<8;q++){
    float4 v0=*(const float4*)&B[(r*8+q)*NN+c*8];
    float4 v1=*(const float4*)&B[(r*8+q)*NN+c*8+4];
    m[q][0]=v0.x; m[q][1]=v0.y; m[q][2]=v0.z; m[q][3]=v0.w;
    m[q][4]=v1.x; m[q][5]=v1.y; m[q][6]=v1.z; m[q][7]=v1.w;
  }
#pragma unroll 1
  for(int k=0;k<NN;k++){
    int par=k&1, kb=k>>3, ke=k&7;
    // publish col k
    if(c==kb){
#pragma unroll
      for(int p=0;p<8;p++) if(p==ke){
#pragma unroll
        for(int q=0;q<8;q++) cb[par][r*8+q]=m[q][p];
        if(r==kb){
#pragma unroll
          for(int q=0;q<8;q++) if(q==ke) pvv[par]=__fdiv_rn(1.0f,m[q][p]);
        }
      }
    }
    // publish row k
    if(r==kb){
#pragma unroll
      for(int q=0;q<8;q++) if(q==ke){
#pragma unroll
        for(int p=0;p<8;p++) rb[par][c*8+p]=m[q][p];
      }
    }
    __syncthreads();
    float pinv=pvv[par];
    float4 r0=*(const float4*)&rb[par][c*8];
    float4 r1=*(const float4*)&rb[par][c*8+4];
    float rv[8]={r0.x,r0.y,r0.z,r0.w,r1.x,r1.y,r1.z,r1.w};
    float4 c0=*(const float4*)&cb[par][r*8];
    float4 c1=*(const float4*)&cb[par][r*8+4];
    float cbv[8]={c0.x,c0.y,c0.z,c0.w,c1.x,c1.y,c1.z,c1.w};
    float nfq[8];
#pragma unroll
    for(int q=0;q<8;q++) nfq[q]=-__fmul_rn(cbv[q],pinv);
    // pure-FMA rank-1 update
#pragma unroll
    for(int q=0;q<8;q++)
#pragma unroll
      for(int p=0;p<8;p++) m[q][p]=__fmaf_rn(nfq[q],rv[p],m[q][p]);
    // fixup row k
    if(r==kb){
#pragma unroll
      for(int q=0;q<8;q++) if(q==ke){
#pragma unroll
        for(int p=0;p<8;p++){ int j=c*8+p;
          m[q][p] = (j==k) ? pinv : __fmul_rn(rv[p],pinv); }
      }
    }
    // fixup col k
    if(c==kb){
#pragma unroll
      for(int p=0;p<8;p++) if(p==ke){
#pragma unroll
        for(int q=0;q<8;q++){ int i=r*8+q;
          if(i!=k) m[q][p]=nfq[q]; }
      }
    }
  }
  const float scf=(float)8.838834764831846e-06;
#pragma unroll
  for(int q=0;q<8;q++)
#pragma unroll
    for(int p=0;p<8;p++)
      B[(r*8+q)*NN+c*8+p]=__fmul_rn(scf,m[q][p]);
}

// ---- K3: A_hat = I - sum_f Cn[f]*D_f ----
__global__ void __launch_bounds__(512,1) k_comb(const float* __restrict__ C){
  __shared__ float cn[NF];
  int g=blockIdx.x, t=threadIdx.x;
  if(t==0){ float s=0; for(int f=0;f<NF;f++) s=__fmaf_rn(C[f],C[f],s);
    float nv=fmaxf(__fsqrt_rn(s),1e-12f);
    for(int f=0;f<NF;f++) cn[f]=__fdiv_rn(C[f],nv); }
  __syncthreads();
  int idx=blockIdx.y*512+t; int i=idx>>7,j=idx&127;
  float s=0;
  for(int f=0;f<NF;f++) s=__fmaf_rn(cn[f],g_D[((size_t)(g*NF+f))*NN2+idx],s);
  g_A[g*NN2+idx]=(i==j)?__fsub_rn(1.0f,s):(-s);
}

// ---- K4: y = A_hat @ feats ----
__global__ void __launch_bounds__(256,2) k_y(const float* __restrict__ x, const float* __restrict__ rs){
  extern __shared__ float sm[];
  float* sA=sm;            // 128*129
  float* sF=sm+NN*P;       // 128*65
  int g=blockIdx.x, cb2=blockIdx.y, t=threadIdx.x, r=t>>4, c=t&15;
  const float scl=(float)sqrt(1.0/1118.0);
  for(int i=t;i<NN2;i+=256) sA[(i>>7)*P+(i&127)]=g_A[g*NN2+i];
  for(int i=t;i<NN*64;i+=256){ int k=i>>6, cc=i&63; int col=cb2*64+cc; float v=0;
    if(col<FD) v=(col<32)? x[(g*NN+k)*32+col] : __fmul_rn(rs[(g*NN+k)*1118+col-32],scl);
    sF[k*65+cc]=v; }
  __syncthreads();
  float a[8][4];
#pragma unroll
  for(int q=0;q<8;q++)
#pragma unroll
    for(int p=0;p<4;p++) a[q][p]=0.f;
  for(int k=0;k<NN;k++){ float av[8],bv[4];
#pragma unroll
    for(int q=0;q<8;q++) av[q]=sA[(r+16*q)*P+k];
#pragma unroll
    for(int p=0;p<4;p++) bv[p]=sF[k*65+c+16*p];
#pragma unroll
    for(int q=0;q<8;q++)
#pragma unroll
      for(int p=0;p<4;p++) a[q][p]=__fmaf_rn(av[q],bv[p],a[q][p]); }
#pragma unroll
  for(int q=0;q<8;q++)
#pragma unroll
    for(int p=0;p<4;p++){ int col=cb2*64+c+16*p;
      if(col<FD) g_y[((size_t)g*NN+r+16*q)*FD+col]=a[q][p]; }
}

// ---- K5: row norms ----
__global__ void k_norm(){
  int g=blockIdx.x, t=threadIdx.x; float s=0;
  const float* yp=g_y+((size_t)g*NN+t)*FD;
  for(int c=0;c<FD;c++){ float v=yp[c]; s=__fmaf_rn(v,v,s); }
  g_norm[g*NN+t]=fmaxf(__fsqrt_rn(s),1e-12f);
}

// ---- K6: gram band -> sum |z z^T| partial ----
__global__ void __launch_bounds__(512,1) k_gram(){
  __shared__ float sY[NN*33];
  __shared__ float red[512];
  int g=blockIdx.x, band=blockIdx.y, t=threadIdx.x;
  int r2=t>>6, c2=t&63;
  float a[4][2];
#pragma unroll
  for(int u=0;u<4;u++)
#pragma unroll
    for(int v=0;v<2;v++) a[u][v]=0.f;
  for(int ch=0;ch<36;ch++){
    __syncthreads();
    for(int i=t;i<NN*32;i+=512){ int row=i>>5, cc=i&31; int col=ch*32+cc;
      sY[row*33+cc]=(col<FD)?g_y[((size_t)g*NN+row)*FD+col]:0.f; }
    __syncthreads();
    for(int kk=0;kk<32;kk++){ float va[4],vb[2];
#pragma unroll
      for(int u=0;u<4;u++) va[u]=sY[(band*32+r2+8*u)*33+kk];
#pragma unroll
      for(int v=0;v<2;v++) vb[v]=sY[(c2+64*v)*33+kk];
#pragma unroll
      for(int u=0;u<4;u++)
#pragma unroll
        for(int v=0;v<2;v++) a[u][v]=__fmaf_rn(va[u],vb[v],a[u][v]); }
  }
  float part=0;
#pragma unroll
  for(int u=0;u<4;u++){ float ni=g_norm[g*NN+band*32+r2+8*u];
#pragma unroll
    for(int v=0;v<2;v++){ float nj=g_norm[g*NN+c2+64*v];
      part+=__fdiv_rn(fabsf(a[u][v]),__fmul_rn(ni,nj)); } }
  red[t]=part; __syncthreads();
  for(int s=256;s>0;s>>=1){ if(t<s) red[t]+=red[t+s]; __syncthreads(); }
  if(t==0) g_spp[g*4+band]=red[0];
}

// ---- K7: emb means ----
__global__ void k_emb(){
  int g=blockIdx.x, c=blockIdx.y*128+threadIdx.x;
  if(c>=FD) return;
  float s=0;
  for(int i=0;i<NN;i++) s+=g_y[((size_t)g*NN+i)*FD+c];
  g_emb[g*FD+c]=s*(1.0f/NN);
}

// ---- K8: pairwise distances ----
__global__ void k_dist(){
  int i=blockIdx.x, j=threadIdx.x;
  const float* ei=g_emb+(size_t)i*FD; const float* ej=g_emb+(size_t)j*FD;
  float d2=0;
  for(int c=0;c<FD;c++){ float d=ei[c]-ej[c]; d2=__fmaf_rn(d,d,d2); }
  g_dist[i*NB+j]=(d2>0.f)?__fsqrt_rn(d2):0.f;
}

// ---- K9: final scalar ----
__global__ void __launch_bounds__(256,1) k_fin(const float* __restrict__ C, float* out){
  __shared__ float rp[256], rn[256];
  int t=threadIdx.x;
  float hl1=0,hl2=0;
  for(int cls=0;cls<4;cls++){
    float ps=0,ns=0;
    for(int p=t;p<NB*NB;p+=256){ int i=p>>6,j=p&63;
      bool pi=((i&3)==cls), pj=((j&3)==cls);
      float d=g_dist[p];
      if(pi&&pj) ps+=d; else if(!pi&&!pj) ns+=d; }
    rp[t]=ps; rn[t]=ns; __syncthreads();
    for(int s=128;s>0;s>>=1){ if(t<s){ rp[t]+=rp[t+s]; rn[t]+=rn[t+s]; } __syncthreads(); }
    if(t==0){ float pm=rp[0]/(16.0f*16.0f), nm=rn[0]/(48.0f*48.0f);
      hl1+=(-nm)/0.25f; hl2+=pm; }
    __syncthreads();
  }
  if(t==0){
    float sf=0, lb=logf(64.0f);
    for(int i=0;i<NB;i++){
      float sp=-(g_spp[i*4]+g_spp[i*4+1]+g_spp[i*4+2]+g_spp[i*4+3])/16384.0f;
      sf+=sp*expf(-(float)(NB-i)*lb); }
    float l1=0,l2=0;
    for(int f=0;f<NF;f++){ l1+=fabsf(C[f]); l2=__fmaf_rn(C[f],C[f],l2); }
    l2=fmaxf(__fsqrt_rn(l2),1e-12f);
    float dims=__fsqrt_rn(21.0f);
    float sc=(dims-__fdiv_rn(l1,l2))/(dims-1.0f);
    *out=sc+hl2+hl1+sf;
  }
}

extern "C" void kernel_launch(void* const* d_in, const int* in_sizes, int n_in,
                              void* d_out, int out_size){
  const float* x=(const float*)d_in[0];
  const float* rs=(const float*)d_in[1];
  const float* C=(const float*)d_in[2];
  const int* es=(const int*)d_in[3];
  const int* ed=(const int*)d_in[4];
  float* out=(float*)d_out;
  static bool init=false;
  if(!init){
    cudaFuncSetAttribute(k_p4, cudaFuncAttributeMaxDynamicSharedMemorySize, NN*P2*4);
    cudaFuncSetAttribute(k_y, cudaFuncAttributeMaxDynamicSharedMemorySize, NN*P*4+NN*65*4);
    init=true;
  }
  k_L<<<NB,256>>>(es,ed);
  k_p4<<<NB*NF,256,NN*P2*4>>>();
  k_inv<<<NB*NF,256>>>();
  k_comb<<<dim3(NB,32),512>>>(C);
  k_y<<<dim3(NB,18),256,NN*P*4+NN*65*4>>>(x,rs);
  k_norm<<<NB,NN>>>();
  k_gram<<<dim3(NB,4),512>>>();
  k_emb<<<dim3(NB,9),128>>>();
  k_dist<<<NB,NB>>>();
  k_fin<<<1,256>>>(C,out);
}